// round 5
// baseline (speedup 1.0000x reference)
#include <cuda_runtime.h>
#include <cstdint>

#define NN 100000
#define NE 1600000
#define SCAN_B 256
#define NBLK ((NN + SCAN_B - 1) / SCAN_B)   // 391

// ---- static device scratch (no allocation allowed) ----
__device__ __align__(16) float g_dinv[NN];
__device__ __align__(16) int   g_src[NE];
__device__ __align__(16) int   g_dst[NE];
__device__ __align__(16) int   g_col[NE];
__device__ __align__(16) int   g_rowptr[NN + 1];
__device__ __align__(16) int   g_deg[NN];
__device__ __align__(16) int   g_scan[NN];
__device__ __align__(16) int   g_cursor[NN];
__device__ __align__(16) int   g_bsum[NBLK];
__device__ __align__(16) int   g_boff[NBLK];
__device__ __align__(16) float g_hs [12800000];   // N x 128 max
__device__ __align__(16) float g_act[12800000];
__device__ int g_is64;

// ---- packed f32x2 helpers (Blackwell FFMA2) ----
typedef unsigned long long u64;
__device__ __forceinline__ u64 pk2(float x, float y) {
    u64 r;
    asm("mov.b64 %0, {%1, %2};" : "=l"(r) : "f"(x), "f"(y));
    return r;
}
__device__ __forceinline__ void upk2(u64 v, float& x, float& y) {
    asm("mov.b64 {%0, %1}, %2;" : "=f"(x), "=f"(y) : "l"(v));
}
__device__ __forceinline__ u64 fma2(u64 a, u64 b, u64 c) {
    u64 d;
    asm("fma.rn.f32x2 %0, %1, %2, %3;" : "=l"(d) : "l"(a), "l"(b), "l"(c));
    return d;
}

// ---------------- dtype sniff ----------------
// int64 nonneg values < 2^31 have zero odd 32-bit words (little-endian).
__global__ void k_sniff(const unsigned int* __restrict__ w) {
    if (threadIdx.x == 0 && blockIdx.x == 0) {
        int is64 = 1;
        for (int i = 0; i < 128; i++)
            if (w[2 * i + 1] != 0u) { is64 = 0; break; }
        g_is64 = is64;
    }
}

// ---------------- CSR build ----------------
__global__ void k_zero_deg() {
    int i = blockIdx.x * blockDim.x + threadIdx.x;
    if (i < NN) g_deg[i] = 0;
}

__global__ void k_prep_edges(const void* __restrict__ ei) {
    int e = blockIdx.x * blockDim.x + threadIdx.x;
    if (e >= NE) return;
    long long s, d;
    if (g_is64) {
        const long long* p = (const long long*)ei;
        s = p[e]; d = p[NE + e];
    } else {
        const int* p = (const int*)ei;
        s = p[e]; d = p[NE + e];
    }
    if (s >= 0 && s < NN && d >= 0 && d < NN) {
        g_src[e] = (int)s;
        g_dst[e] = (int)d;
        atomicAdd(&g_deg[(int)d], 1);
    } else {
        g_src[e] = -1;   // sentinel
        g_dst[e] = 0;
    }
}

__global__ void k_scan1() {
    __shared__ int sm[SCAN_B];
    int tid = threadIdx.x;
    int i = blockIdx.x * SCAN_B + tid;
    sm[tid] = (i < NN) ? g_deg[i] : 0;
    __syncthreads();
#pragma unroll
    for (int off = 1; off < SCAN_B; off <<= 1) {
        int t = (tid >= off) ? sm[tid - off] : 0;
        __syncthreads();
        if (tid >= off) sm[tid] += t;
        __syncthreads();
    }
    if (i < NN) g_scan[i] = sm[tid];
    if (tid == SCAN_B - 1) g_bsum[blockIdx.x] = sm[SCAN_B - 1];
}

__global__ void k_scan2() {
    __shared__ int sm[512];
    int tid = threadIdx.x;
    sm[tid] = (tid < NBLK) ? g_bsum[tid] : 0;
    __syncthreads();
#pragma unroll
    for (int off = 1; off < 512; off <<= 1) {
        int t = (tid >= off) ? sm[tid - off] : 0;
        __syncthreads();
        if (tid >= off) sm[tid] += t;
        __syncthreads();
    }
    if (tid < NBLK) g_boff[tid] = sm[tid] - g_bsum[tid];   // exclusive
}

__global__ void k_finalize_csr() {
    int i = blockIdx.x * blockDim.x + threadIdx.x;
    if (i >= NN) return;
    int incl = g_scan[i] + g_boff[i / SCAN_B];
    int deg = g_deg[i];
    g_rowptr[i] = incl - deg;
    g_cursor[i] = 0;
    g_dinv[i] = rsqrtf((float)deg + 1.0f);
    if (i == NN - 1) g_rowptr[NN] = incl;
}

__global__ void k_fill() {
    int e = blockIdx.x * blockDim.x + threadIdx.x;
    if (e >= NE) return;
    int s = g_src[e];
    if (s < 0) return;
    int d = g_dst[e];
    int pos = g_rowptr[d] + atomicAdd(&g_cursor[d], 1);
    g_col[pos] = s;
}

// ---------------- GEMM, layer 1 (128x128), packed f32x2 ----------------
// BM=128, BN=128, BK=16, 256 threads, 8x8 per-thread tile (4 u64 accs per row).
// Epilogue: hs = acc*dinv[row].
__global__ __launch_bounds__(256) void gemm128(const float* __restrict__ in,
                                               const float* __restrict__ W) {
    __shared__ __align__(16) float xs[16][136];   // k-major, padded
    __shared__ __align__(16) float ws[16][128];
    int tid = threadIdx.x;
    int tx = tid & 15, ty = tid >> 4;
    int rowBase = blockIdx.x * 128;
    u64 acc2[8][4];
    const u64 z = 0;
#pragma unroll
    for (int i = 0; i < 8; i++)
#pragma unroll
        for (int j = 0; j < 4; j++) acc2[i][j] = z;

    for (int k0 = 0; k0 < 128; k0 += 16) {
#pragma unroll
        for (int i = 0; i < 8; i++) {
            int idx = tid + i * 256;
            int m = idx >> 4, c = idx & 15;
            int gr = rowBase + m;
            xs[c][m] = (gr < NN) ? in[gr * 128 + k0 + c] : 0.0f;
        }
#pragma unroll
        for (int i = 0; i < 8; i++) {
            int idx = tid + i * 256;
            int k = idx >> 7, j = idx & 127;
            ws[k][j] = W[(k0 + k) * 128 + j];
        }
        __syncthreads();
#pragma unroll
        for (int k = 0; k < 16; k++) {
            float4 rm0 = *(const float4*)&xs[k][ty * 8];
            float4 rm1 = *(const float4*)&xs[k][ty * 8 + 4];
            u64 a2[8];
            a2[0] = pk2(rm0.x, rm0.x); a2[1] = pk2(rm0.y, rm0.y);
            a2[2] = pk2(rm0.z, rm0.z); a2[3] = pk2(rm0.w, rm0.w);
            a2[4] = pk2(rm1.x, rm1.x); a2[5] = pk2(rm1.y, rm1.y);
            a2[6] = pk2(rm1.z, rm1.z); a2[7] = pk2(rm1.w, rm1.w);
            u64 b2[4];
#pragma unroll
            for (int j = 0; j < 4; j++)
                b2[j] = *(const u64*)&ws[k][tx * 8 + 2 * j];
#pragma unroll
            for (int i = 0; i < 8; i++)
#pragma unroll
                for (int j = 0; j < 4; j++)
                    acc2[i][j] = fma2(a2[i], b2[j], acc2[i][j]);
        }
        __syncthreads();
    }

#pragma unroll
    for (int i = 0; i < 8; i++) {
        int row = rowBase + ty * 8 + i;
        if (row < NN) {
            float dv = g_dinv[row];
#pragma unroll
            for (int j = 0; j < 2; j++) {   // two float4 stores
                float l0, h0, l1, h1;
                upk2(acc2[i][2 * j + 0], l0, h0);
                upk2(acc2[i][2 * j + 1], l1, h1);
                float4 v;
                v.x = l0 * dv; v.y = h0 * dv;
                v.z = l1 * dv; v.w = h1 * dv;
                *(float4*)&g_hs[row * 128 + tx * 8 + j * 4] = v;
            }
        }
    }
}

// ---------------- GEMM, layers 2-5 (FOUT <= 64), packed f32x2 ----------------
// one thread per output row; full W in smem; x staged in BK=8 smem tiles
template <int FIN, int FOUT>
__global__ __launch_bounds__(256) void gemm_small(const float* __restrict__ in,
                                                  const float* __restrict__ W) {
    __shared__ __align__(16) float ws[FIN * FOUT];
    __shared__ __align__(16) float xs[256][9];    // BK=8, padded
    int tid = threadIdx.x;
    for (int i = tid; i < FIN * FOUT; i += 256) ws[i] = W[i];

    int rowBase = blockIdx.x * 256;
    int row = rowBase + tid;
    u64 acc2[FOUT / 2];
#pragma unroll
    for (int j = 0; j < FOUT / 2; j++) acc2[j] = 0;

    for (int k0 = 0; k0 < FIN; k0 += 8) {
#pragma unroll
        for (int i = 0; i < 8; i++) {
            int idx = tid + i * 256;
            int r = idx >> 3, c = idx & 7;
            int gr = rowBase + r;
            xs[r][c] = (gr < NN) ? in[gr * FIN + k0 + c] : 0.0f;
        }
        __syncthreads();
#pragma unroll
        for (int k = 0; k < 8; k++) {
            float xv = xs[tid][k];
            u64 a2 = pk2(xv, xv);
            const u64* wrow = (const u64*)&ws[(k0 + k) * FOUT];
#pragma unroll
            for (int j = 0; j < FOUT / 2; j++)
                acc2[j] = fma2(a2, wrow[j], acc2[j]);
        }
        __syncthreads();
    }

    if (row < NN) {
        float dv = g_dinv[row];
#pragma unroll
        for (int j = 0; j < FOUT / 4; j++) {
            float l0, h0, l1, h1;
            upk2(acc2[2 * j + 0], l0, h0);
            upk2(acc2[2 * j + 1], l1, h1);
            float4 v;
            v.x = l0 * dv; v.y = h0 * dv;
            v.z = l1 * dv; v.w = h1 * dv;
            *(float4*)&g_hs[row * FOUT + j * 4] = v;
        }
    }
}

// ---------------- fused aggregate + bias + relu ----------------
// subwarp of F/4 lanes per node; acc = hs[self] + sum_{nbr} hs[nbr];
// out = relu(dinv*acc + b)
template <int F>
__global__ __launch_bounds__(256) void aggregate(const float* __restrict__ bias,
                                                 float* __restrict__ outp) {
    constexpr int L = F / 4;        // lanes per node
    constexpr int NPW = 32 / L;     // nodes per warp
    int warp = (blockIdx.x * 256 + threadIdx.x) >> 5;
    int lane = threadIdx.x & 31;
    int node = warp * NPW + lane / L;
    int c4 = (lane % L) * 4;        // float offset of this lane's chunk
    if (node >= NN) return;

    int beg = g_rowptr[node];
    int end = g_rowptr[node + 1];
    float4 acc = *(const float4*)&g_hs[(size_t)node * F + c4];

    int e = beg;
    for (; e + 1 < end; e += 2) {
        int s0 = g_col[e];
        int s1 = g_col[e + 1];
        float4 v0 = *(const float4*)&g_hs[(size_t)s0 * F + c4];
        float4 v1 = *(const float4*)&g_hs[(size_t)s1 * F + c4];
        acc.x += v0.x + v1.x;
        acc.y += v0.y + v1.y;
        acc.z += v0.z + v1.z;
        acc.w += v0.w + v1.w;
    }
    if (e < end) {
        int s = g_col[e];
        float4 v = *(const float4*)&g_hs[(size_t)s * F + c4];
        acc.x += v.x; acc.y += v.y; acc.z += v.z; acc.w += v.w;
    }

    float dv = g_dinv[node];
    float4 b = *(const float4*)&bias[c4];
    float4 r;
    r.x = fmaxf(fmaf(dv, acc.x, b.x), 0.0f);
    r.y = fmaxf(fmaf(dv, acc.y, b.y), 0.0f);
    r.z = fmaxf(fmaf(dv, acc.z, b.z), 0.0f);
    r.w = fmaxf(fmaf(dv, acc.w, b.w), 0.0f);
    *(float4*)&outp[(size_t)node * F + c4] = r;
}

template <int F>
static inline int agg_blocks() {
    int npw = 32 / (F / 4);
    int nodes_per_block = npw * 8;
    return (NN + nodes_per_block - 1) / nodes_per_block;
}

// ---------------- launch ----------------
extern "C" void kernel_launch(void* const* d_in, const int* in_sizes, int n_in,
                              void* d_out, int out_size) {
    const float* x  = (const float*)d_in[0];
    const void*  ei = d_in[1];
    const float* W1 = (const float*)d_in[2];
    const float* b1 = (const float*)d_in[3];
    const float* W2 = (const float*)d_in[4];
    const float* b2 = (const float*)d_in[5];
    const float* W3 = (const float*)d_in[6];
    const float* b3 = (const float*)d_in[7];
    const float* W4 = (const float*)d_in[8];
    const float* b4 = (const float*)d_in[9];
    const float* W5 = (const float*)d_in[10];
    const float* b5 = (const float*)d_in[11];
    float* out = (float*)d_out;

    static float* act = nullptr;
    if (!act) cudaGetSymbolAddress((void**)&act, g_act);

    int nb = (NN + 255) / 256;
    int eb = (NE + 255) / 256;

    // graph prep + CSR build
    k_sniff        <<<1, 32>>>((const unsigned int*)ei);
    k_zero_deg     <<<nb, 256>>>();
    k_prep_edges   <<<eb, 256>>>(ei);
    k_scan1        <<<NBLK, SCAN_B>>>();
    k_scan2        <<<1, 512>>>();
    k_finalize_csr <<<nb, 256>>>();
    k_fill         <<<eb, 256>>>();

    // Layer 1: 128 -> 128
    gemm128        <<<(NN + 127) / 128, 256>>>(x, W1);
    aggregate<128> <<<agg_blocks<128>(), 256>>>(b1, act);

    // Layer 2: 128 -> 64
    gemm_small<128, 64><<<nb, 256>>>(act, W2);
    aggregate<64>  <<<agg_blocks<64>(), 256>>>(b2, act);

    // Layer 3: 64 -> 32
    gemm_small<64, 32><<<nb, 256>>>(act, W3);
    aggregate<32>  <<<agg_blocks<32>(), 256>>>(b3, act);

    // Layer 4: 32 -> 16
    gemm_small<32, 16><<<nb, 256>>>(act, W4);
    aggregate<16>  <<<agg_blocks<16>(), 256>>>(b4, act);

    // Layer 5: 16 -> 8 (output)
    gemm_small<16, 8><<<nb, 256>>>(act, W5);
    aggregate<8>   <<<agg_blocks<8>(), 256>>>(b5, out);
}

// round 6
// speedup vs baseline: 1.0949x; 1.0949x over previous
#include <cuda_runtime.h>
#include <cstdint>

#define NN 100000
#define NE 1600000
#define SCAN_B 256
#define NBLK ((NN + SCAN_B - 1) / SCAN_B)   // 391

// ---- static device scratch (no allocation allowed) ----
__device__ __align__(16) float g_dinv[NN];
__device__ __align__(16) int   g_src[NE];
__device__ __align__(16) int   g_dst[NE];
__device__ __align__(16) int   g_col[NE];
__device__ __align__(16) int   g_rowptr[NN + 1];
__device__ __align__(16) int   g_deg[NN];
__device__ __align__(16) int   g_scan[NN];
__device__ __align__(16) int   g_cursor[NN];
__device__ __align__(16) int   g_bsum[NBLK];
__device__ __align__(16) int   g_boff[NBLK];
__device__ __align__(16) float g_hs [12800000];   // N x 128 max
__device__ __align__(16) float g_act[12800000];
__device__ int g_is64;

// ---------------- dtype sniff ----------------
// int64 nonneg values < 2^31 have zero odd 32-bit words (little-endian).
__global__ void k_sniff(const unsigned int* __restrict__ w) {
    if (threadIdx.x == 0 && blockIdx.x == 0) {
        int is64 = 1;
        for (int i = 0; i < 128; i++)
            if (w[2 * i + 1] != 0u) { is64 = 0; break; }
        g_is64 = is64;
    }
}

// ---------------- CSR build ----------------
__global__ void k_zero_deg() {
    int i = blockIdx.x * blockDim.x + threadIdx.x;
    if (i < NN) g_deg[i] = 0;
}

__global__ void k_prep_edges(const void* __restrict__ ei) {
    int e = blockIdx.x * blockDim.x + threadIdx.x;
    if (e >= NE) return;
    long long s, d;
    if (g_is64) {
        const long long* p = (const long long*)ei;
        s = p[e]; d = p[NE + e];
    } else {
        const int* p = (const int*)ei;
        s = p[e]; d = p[NE + e];
    }
    if (s >= 0 && s < NN && d >= 0 && d < NN) {
        g_src[e] = (int)s;
        g_dst[e] = (int)d;
        atomicAdd(&g_deg[(int)d], 1);
    } else {
        g_src[e] = -1;   // sentinel
        g_dst[e] = 0;
    }
}

__global__ void k_scan1() {
    __shared__ int sm[SCAN_B];
    int tid = threadIdx.x;
    int i = blockIdx.x * SCAN_B + tid;
    sm[tid] = (i < NN) ? g_deg[i] : 0;
    __syncthreads();
#pragma unroll
    for (int off = 1; off < SCAN_B; off <<= 1) {
        int t = (tid >= off) ? sm[tid - off] : 0;
        __syncthreads();
        if (tid >= off) sm[tid] += t;
        __syncthreads();
    }
    if (i < NN) g_scan[i] = sm[tid];
    if (tid == SCAN_B - 1) g_bsum[blockIdx.x] = sm[SCAN_B - 1];
}

__global__ void k_scan2() {
    __shared__ int sm[512];
    int tid = threadIdx.x;
    sm[tid] = (tid < NBLK) ? g_bsum[tid] : 0;
    __syncthreads();
#pragma unroll
    for (int off = 1; off < 512; off <<= 1) {
        int t = (tid >= off) ? sm[tid - off] : 0;
        __syncthreads();
        if (tid >= off) sm[tid] += t;
        __syncthreads();
    }
    if (tid < NBLK) g_boff[tid] = sm[tid] - g_bsum[tid];   // exclusive
}

__global__ void k_finalize_csr() {
    int i = blockIdx.x * blockDim.x + threadIdx.x;
    if (i >= NN) return;
    int incl = g_scan[i] + g_boff[i / SCAN_B];
    int deg = g_deg[i];
    g_rowptr[i] = incl - deg;
    g_cursor[i] = 0;
    g_dinv[i] = rsqrtf((float)deg + 1.0f);
    if (i == NN - 1) g_rowptr[NN] = incl;
}

__global__ void k_fill() {
    int e = blockIdx.x * blockDim.x + threadIdx.x;
    if (e >= NE) return;
    int s = g_src[e];
    if (s < 0) return;
    int d = g_dst[e];
    int pos = g_rowptr[d] + atomicAdd(&g_cursor[d], 1);
    g_col[pos] = s;
}

// ---------------- GEMM, layer 1 (128x128), double-buffered ----------------
// BM=128, BN=128, BK=16, 256 threads, 8x8 per-thread tile. Writes RAW h
// (dinv scaling deferred to aggregate).
__global__ __launch_bounds__(256) void gemm128(const float* __restrict__ in,
                                               const float* __restrict__ W) {
    __shared__ __align__(16) float xs[2][16][136];   // k-major, padded
    __shared__ __align__(16) float ws[2][16][128];
    int tid = threadIdx.x;
    int tx = tid & 15, ty = tid >> 4;
    int rowBase = blockIdx.x * 128;
    float acc[8][8];
#pragma unroll
    for (int i = 0; i < 8; i++)
#pragma unroll
        for (int j = 0; j < 8; j++) acc[i][j] = 0.0f;

    // prologue: load tile 0
#pragma unroll
    for (int i = 0; i < 8; i++) {
        int idx = tid + i * 256;
        int m = idx >> 4, c = idx & 15;
        int gr = rowBase + m;
        xs[0][c][m] = (gr < NN) ? in[gr * 128 + c] : 0.0f;
    }
#pragma unroll
    for (int i = 0; i < 8; i++) {
        int idx = tid + i * 256;
        int k = idx >> 7, j = idx & 127;
        ws[0][k][j] = W[k * 128 + j];
    }
    __syncthreads();

    for (int kt = 0; kt < 8; kt++) {
        int buf = kt & 1;
        if (kt < 7) {
            int k0 = (kt + 1) * 16;
            int nb = buf ^ 1;
#pragma unroll
            for (int i = 0; i < 8; i++) {
                int idx = tid + i * 256;
                int m = idx >> 4, c = idx & 15;
                int gr = rowBase + m;
                xs[nb][c][m] = (gr < NN) ? in[gr * 128 + k0 + c] : 0.0f;
            }
#pragma unroll
            for (int i = 0; i < 8; i++) {
                int idx = tid + i * 256;
                int k = idx >> 7, j = idx & 127;
                ws[nb][k][j] = W[(k0 + k) * 128 + j];
            }
        }
#pragma unroll
        for (int k = 0; k < 16; k++) {
            float rm[8], rn[8];
            *(float4*)&rm[0] = *(const float4*)&xs[buf][k][ty * 8];
            *(float4*)&rm[4] = *(const float4*)&xs[buf][k][ty * 8 + 4];
            *(float4*)&rn[0] = *(const float4*)&ws[buf][k][tx * 8];
            *(float4*)&rn[4] = *(const float4*)&ws[buf][k][tx * 8 + 4];
#pragma unroll
            for (int i = 0; i < 8; i++)
#pragma unroll
                for (int j = 0; j < 8; j++)
                    acc[i][j] = fmaf(rm[i], rn[j], acc[i][j]);
        }
        __syncthreads();
    }

#pragma unroll
    for (int i = 0; i < 8; i++) {
        int row = rowBase + ty * 8 + i;
        if (row < NN) {
#pragma unroll
            for (int j = 0; j < 8; j += 4) {
                float4 v;
                v.x = acc[i][j + 0];
                v.y = acc[i][j + 1];
                v.z = acc[i][j + 2];
                v.w = acc[i][j + 3];
                *(float4*)&g_hs[row * 128 + tx * 8 + j] = v;
            }
        }
    }
}

// ---------------- GEMM, layers 2-5 (FOUT <= 64) ----------------
// one thread per output row; full W in smem; x staged in BK=8 smem tiles.
// Writes RAW h.
template <int FIN, int FOUT>
__global__ __launch_bounds__(256) void gemm_small(const float* __restrict__ in,
                                                  const float* __restrict__ W) {
    __shared__ float ws[FIN * FOUT];
    __shared__ float xs[256][9];    // BK=8, padded
    int tid = threadIdx.x;
    for (int i = tid; i < FIN * FOUT; i += 256) ws[i] = W[i];

    int rowBase = blockIdx.x * 256;
    int row = rowBase + tid;
    float acc[FOUT];
#pragma unroll
    for (int j = 0; j < FOUT; j++) acc[j] = 0.0f;

    for (int k0 = 0; k0 < FIN; k0 += 8) {
#pragma unroll
        for (int i = 0; i < 8; i++) {
            int idx = tid + i * 256;
            int r = idx >> 3, c = idx & 7;
            int gr = rowBase + r;
            xs[r][c] = (gr < NN) ? in[gr * FIN + k0 + c] : 0.0f;
        }
        __syncthreads();
#pragma unroll
        for (int k = 0; k < 8; k++) {
            float xv = xs[tid][k];
            const float* wrow = &ws[(k0 + k) * FOUT];
#pragma unroll
            for (int j = 0; j < FOUT; j++)
                acc[j] = fmaf(xv, wrow[j], acc[j]);
        }
        __syncthreads();
    }

    if (row < NN) {
#pragma unroll
        for (int j = 0; j < FOUT; j += 4) {
            float4 v;
            v.x = acc[j + 0];
            v.y = acc[j + 1];
            v.z = acc[j + 2];
            v.w = acc[j + 3];
            *(float4*)&g_hs[row * FOUT + j] = v;
        }
    }
}

// ---------------- fused aggregate + norm + bias + relu ----------------
// h is RAW; out[n] = relu(dinv[n]*(dinv[n]*h[n] + sum_s dinv[s]*h[s]) + b)
template <int F>
__global__ __launch_bounds__(256) void aggregate(const float* __restrict__ bias,
                                                 float* __restrict__ outp) {
    constexpr int L = F / 4;        // lanes per node
    constexpr int NPW = 32 / L;     // nodes per warp
    int warp = (blockIdx.x * 256 + threadIdx.x) >> 5;
    int lane = threadIdx.x & 31;
    int node = warp * NPW + lane / L;
    int c4 = (lane % L) * 4;        // float offset of this lane's chunk
    if (node >= NN) return;

    float dvn = g_dinv[node];
    int beg = g_rowptr[node];
    int end = g_rowptr[node + 1];
    float4 hv = *(const float4*)&g_hs[(size_t)node * F + c4];
    float4 acc;
    acc.x = dvn * hv.x; acc.y = dvn * hv.y;
    acc.z = dvn * hv.z; acc.w = dvn * hv.w;

    int e = beg;
    for (; e + 1 < end; e += 2) {
        int s0 = g_col[e];
        int s1 = g_col[e + 1];
        float d0 = g_dinv[s0];
        float d1 = g_dinv[s1];
        float4 v0 = *(const float4*)&g_hs[(size_t)s0 * F + c4];
        float4 v1 = *(const float4*)&g_hs[(size_t)s1 * F + c4];
        acc.x = fmaf(d0, v0.x, fmaf(d1, v1.x, acc.x));
        acc.y = fmaf(d0, v0.y, fmaf(d1, v1.y, acc.y));
        acc.z = fmaf(d0, v0.z, fmaf(d1, v1.z, acc.z));
        acc.w = fmaf(d0, v0.w, fmaf(d1, v1.w, acc.w));
    }
    if (e < end) {
        int s = g_col[e];
        float ds = g_dinv[s];
        float4 v = *(const float4*)&g_hs[(size_t)s * F + c4];
        acc.x = fmaf(ds, v.x, acc.x);
        acc.y = fmaf(ds, v.y, acc.y);
        acc.z = fmaf(ds, v.z, acc.z);
        acc.w = fmaf(ds, v.w, acc.w);
    }

    float4 b = *(const float4*)&bias[c4];
    float4 r;
    r.x = fmaxf(fmaf(dvn, acc.x, b.x), 0.0f);
    r.y = fmaxf(fmaf(dvn, acc.y, b.y), 0.0f);
    r.z = fmaxf(fmaf(dvn, acc.z, b.z), 0.0f);
    r.w = fmaxf(fmaf(dvn, acc.w, b.w), 0.0f);
    *(float4*)&outp[(size_t)node * F + c4] = r;
}

template <int F>
static inline int agg_blocks() {
    int npw = 32 / (F / 4);
    int nodes_per_block = npw * 8;
    return (NN + nodes_per_block - 1) / nodes_per_block;
}

// ---------------- launch ----------------
extern "C" void kernel_launch(void* const* d_in, const int* in_sizes, int n_in,
                              void* d_out, int out_size) {
    const float* x  = (const float*)d_in[0];
    const void*  ei = d_in[1];
    const float* W1 = (const float*)d_in[2];
    const float* b1 = (const float*)d_in[3];
    const float* W2 = (const float*)d_in[4];
    const float* b2 = (const float*)d_in[5];
    const float* W3 = (const float*)d_in[6];
    const float* b3 = (const float*)d_in[7];
    const float* W4 = (const float*)d_in[8];
    const float* b4 = (const float*)d_in[9];
    const float* W5 = (const float*)d_in[10];
    const float* b5 = (const float*)d_in[11];
    float* out = (float*)d_out;

    static float* act = nullptr;
    static cudaStream_t s1 = nullptr;
    static cudaEvent_t evA = nullptr, evB = nullptr;
    if (!act) {
        cudaGetSymbolAddress((void**)&act, g_act);
        cudaStreamCreateWithFlags(&s1, cudaStreamNonBlocking);
        cudaEventCreateWithFlags(&evA, cudaEventDisableTiming);
        cudaEventCreateWithFlags(&evB, cudaEventDisableTiming);
    }

    int nb = (NN + 255) / 256;
    int eb = (NE + 255) / 256;

    // fork: CSR build on s1, layer-1 GEMM (edge-independent) on main stream
    cudaEventRecord(evA, 0);
    cudaStreamWaitEvent(s1, evA, 0);

    k_sniff        <<<1, 32, 0, s1>>>((const unsigned int*)ei);
    k_zero_deg     <<<nb, 256, 0, s1>>>();
    k_prep_edges   <<<eb, 256, 0, s1>>>(ei);
    k_scan1        <<<NBLK, SCAN_B, 0, s1>>>();
    k_scan2        <<<1, 512, 0, s1>>>();
    k_finalize_csr <<<nb, 256, 0, s1>>>();
    k_fill         <<<eb, 256, 0, s1>>>();
    cudaEventRecord(evB, s1);

    gemm128        <<<(NN + 127) / 128, 256>>>(x, W1);

    // join: aggregation needs CSR + dinv
    cudaStreamWaitEvent(0, evB, 0);

    // Layer 1: 128 -> 128
    aggregate<128> <<<agg_blocks<128>(), 256>>>(b1, act);

    // Layer 2: 128 -> 64
    gemm_small<128, 64><<<nb, 256>>>(act, W2);
    aggregate<64>  <<<agg_blocks<64>(), 256>>>(b2, act);

    // Layer 3: 64 -> 32
    gemm_small<64, 32><<<nb, 256>>>(act, W3);
    aggregate<32>  <<<agg_blocks<32>(), 256>>>(b3, act);

    // Layer 4: 32 -> 16
    gemm_small<32, 16><<<nb, 256>>>(act, W4);
    aggregate<16>  <<<agg_blocks<16>(), 256>>>(b4, act);

    // Layer 5: 16 -> 8 (output)
    gemm_small<16, 8><<<nb, 256>>>(act, W5);
    aggregate<8>   <<<agg_blocks<8>(), 256>>>(b5, out);
}